// round 3
// baseline (speedup 1.0000x reference)
#include <cuda_runtime.h>

#define B_  8
#define C_  256
#define C8  32
#define H_  96
#define W_  96
#define HW  9216
#define PP  280

// ---------------- scratch (device globals; no allocation allowed) ----------------
__device__ float g_P1[B_*C_*PP];     // PSP(x_1)  [8,256,280]
__device__ float g_P2[B_*C_*PP];     // PSP(x)    [8,256,280]
__device__ float g_pk[B_*C8*PP];     // projk     [8,32,280]
__device__ float g_S [B_*C8];        // sum_p projk
__device__ float g_G [B_*C_*C8];     // P1 . projk^T  [8,256,32]
__device__ float g_aff[B_*C_*C8];    // sigmoid(...)  [8,256,32]
__device__ float g_ya[B_*C8*HW];     // conv partial (c 0..127)
__device__ float g_yb[B_*C8*HW];     // conv partial (c 128..255)

// ---------------- f32x2 helpers (Blackwell packed fp32) ----------------
__device__ __forceinline__ unsigned long long pk2f(float lo, float hi) {
    unsigned long long r;
    asm("mov.b64 %0, {%1, %2};" : "=l"(r) : "f"(lo), "f"(hi));
    return r;
}
__device__ __forceinline__ void upk2f(unsigned long long v, float& lo, float& hi) {
    asm("mov.b64 {%0, %1}, %2;" : "=f"(lo), "=f"(hi) : "l"(v));
}
__device__ __forceinline__ void fma2(unsigned long long& acc,
                                     unsigned long long a, unsigned long long b) {
    asm("fma.rn.f32x2 %0, %1, %2, %0;" : "+l"(acc) : "l"(a), "l"(b));
}

// ---------------- K1: adaptive pyramid pooling (both tensors) ----------------
// grid 2*B*C blocks; one (tensor, b*C+c) channel per block.
__global__ void __launch_bounds__(256) pool_kernel(const float* __restrict__ x1,
                                                   const float* __restrict__ x2) {
    __shared__ float tile[96][97];     // 37248 B (pad 97 kills column bank conflicts)
    __shared__ float rb[30][96];       // 11520 B  -> total 48768 B (<= 48KB)
    int idx = blockIdx.x;
    int sel = idx >> 11;               // 0: x_1 -> P1, 1: x -> P2
    int ch  = idx & 2047;              // b*C + c
    const float* src = sel ? x2 : x1;
    float* dst = sel ? g_P2 : g_P1;

    const float4* s4 = (const float4*)(src + (size_t)ch * HW);
    for (int i = threadIdx.x; i < HW / 4; i += 256) {
        float4 v = s4[i];
        int li = i * 4, r = li / 96, c0 = li % 96;
        tile[r][c0] = v.x; tile[r][c0+1] = v.y; tile[r][c0+2] = v.z; tile[r][c0+3] = v.w;
    }
    __syncthreads();

    // 30 1D row-bins (sizes 1,3,5,7,14; bins may overlap -> exact boundaries)
    for (int t = threadIdx.x; t < 30 * 96; t += 256) {
        int bin = t / 96, w = t % 96, s, i;
        if      (bin == 0) { s = 1;  i = 0; }
        else if (bin < 4)  { s = 3;  i = bin - 1; }
        else if (bin < 9)  { s = 5;  i = bin - 4; }
        else if (bin < 16) { s = 7;  i = bin - 9; }
        else               { s = 14; i = bin - 16; }
        int rs = (i * 96) / s, re = ((i + 1) * 96 + s - 1) / s;
        float sum = 0.f;
        for (int h = rs; h < re; h++) sum += tile[h][w];
        rb[bin][w] = sum;
    }
    __syncthreads();

    for (int p = threadIdx.x; p < PP; p += 256) {
        int s, base, rbb;
        if      (p < 1)  { s = 1;  base = 0;  rbb = 0; }
        else if (p < 10) { s = 3;  base = 1;  rbb = 1; }
        else if (p < 35) { s = 5;  base = 10; rbb = 4; }
        else if (p < 84) { s = 7;  base = 35; rbb = 9; }
        else             { s = 14; base = 84; rbb = 16; }
        int q = p - base, i = q / s, j = q % s;
        int rs = (i * 96) / s, re = ((i + 1) * 96 + s - 1) / s;
        int cs = (j * 96) / s, ce = ((j + 1) * 96 + s - 1) / s;
        float sum = 0.f;
        for (int w = cs; w < ce; w++) sum += rb[rbb + i][w];
        dst[(size_t)ch * PP + p] = sum / (float)((re - rs) * (ce - cs));
    }
}

// ---------------- K2: projk = wk @ P2 + bk  (grid: 10 p-tiles x 8 b) ----------------
__global__ void __launch_bounds__(256) projk_kernel(const float* __restrict__ wk,
                                                    const float* __restrict__ bk) {
    __shared__ float pt[256][28];      // 28672 B
    int b = blockIdx.y, p0 = blockIdx.x * 28;
    for (int i = threadIdx.x; i < 256 * 28; i += 256) {
        int c = i / 28, pp = i % 28;
        pt[c][pp] = g_P2[((size_t)(b * 256 + c)) * PP + p0 + pp];
    }
    __syncthreads();
    for (int oi = threadIdx.x; oi < 32 * 28; oi += 256) {
        int j = oi / 28, pp = oi % 28;
        float sum = 0.f;
        #pragma unroll 8
        for (int c = 0; c < 256; c++)
            sum += __ldg(wk + j * 256 + c) * pt[c][pp];   // wk warp-uniform -> L1 bcast
        g_pk[((size_t)(b * 32 + j)) * PP + p0 + pp] = bk[j] + sum;
    }
}

// ---------------- K3: S[b,j] = sum_p projk ----------------
__global__ void s_kernel() {
    int b = blockIdx.x, j = threadIdx.x;
    const float* r = g_pk + ((size_t)(b * 32 + j)) * PP;
    float s = 0.f;
    for (int p = 0; p < PP; p++) s += r[p];
    g_S[b * 32 + j] = s;
}

// ---------------- K4: G[b,c,j] = sum_p P1[b,c,p]*projk[b,j,p] ----------------
// grid: (4 c-tiles of 64) x 8 b; 256 thr: c = tile*64 + tid/4, jg = (tid&3)*8
__global__ void __launch_bounds__(256) gmat_kernel() {
    __shared__ float pk_s[32 * 281];   // pad 281 -> distinct banks for jg in {0,8,16,24}
    int b = blockIdx.y, c = blockIdx.x * 64 + (threadIdx.x >> 2);
    int jg = (threadIdx.x & 3) * 8;
    for (int i = threadIdx.x; i < 32 * 280; i += 256)
        pk_s[(i / 280) * 281 + (i % 280)] = g_pk[(size_t)b * 32 * PP + i];
    __syncthreads();
    const float* p1 = g_P1 + ((size_t)(b * 256 + c)) * PP;
    float acc[8];
    #pragma unroll
    for (int k = 0; k < 8; k++) acc[k] = 0.f;
    for (int p = 0; p < PP; p++) {
        float xv = __ldg(p1 + p);
        #pragma unroll
        for (int k = 0; k < 8; k++) acc[k] += xv * pk_s[(jg + k) * 281 + p];
    }
    #pragma unroll
    for (int k = 0; k < 8; k++)
        g_G[((size_t)(b * 256 + c)) * 32 + jg + k] = acc[k];
}

// ---------------- K5: aff = sigmoid(wq @ G + bq*S) ----------------
// grid: (16 o-tiles of 16) x 8 b; 128 thr = 16 o x 8 c-groups; shuffle-reduce.
__global__ void __launch_bounds__(128) aff_kernel(const float* __restrict__ wq,
                                                  const float* __restrict__ bq) {
    __shared__ float Gs[256 * 33];     // pad 33 -> conflict-free (c stride 1 per lane)
    int b = blockIdx.y;
    int o = blockIdx.x * 16 + (threadIdx.x >> 3);
    int cg = threadIdx.x & 7;
    for (int i = threadIdx.x; i < 8192; i += 128)
        Gs[(i >> 5) * 33 + (i & 31)] = g_G[(size_t)b * 8192 + i];
    __syncthreads();
    float acc[32];
    #pragma unroll
    for (int j = 0; j < 32; j++) acc[j] = 0.f;
    for (int cc = 0; cc < 32; cc++) {
        int c = cg + cc * 8;
        float wv = __ldg(wq + o * 256 + c);
        #pragma unroll
        for (int j = 0; j < 32; j++) acc[j] += wv * Gs[c * 33 + j];
    }
    // reduce across the 8 c-groups (lanes cg 0..7 within each 8-lane group)
    #pragma unroll
    for (int j = 0; j < 32; j++) {
        acc[j] += __shfl_xor_sync(0xffffffffu, acc[j], 1);
        acc[j] += __shfl_xor_sync(0xffffffffu, acc[j], 2);
        acc[j] += __shfl_xor_sync(0xffffffffu, acc[j], 4);
    }
    if (cg == 0) {
        float bqo = __ldg(bq + o);
        #pragma unroll
        for (int j = 0; j < 32; j++) {
            float z = acc[j] + bqo * g_S[b * 32 + j];
            g_aff[((size_t)(b * 256 + o)) * 32 + j] = 1.f / (1.f + expf(-z));
        }
    }
}

// ---------------- K6: y = conv3x3(x_1, con), split into 2 c-halves ----------------
// grid: (9 spatial 32x32 tiles) x 8 b x 2 c-halves; 256 thr; thread = 4-wide row strip.
// All 32 output channels held in f32x2 register accumulators (one input read per c).
__global__ void __launch_bounds__(256, 1) conv_kernel(const float* __restrict__ x1,
                                                      const float* __restrict__ con) {
    __shared__ __align__(16) float in_s[4][34][36];   // 19584 B
    __shared__ float2 w_s[4][32][9];                  // 9216 B (weights duplicated for LDS.64)
    int tile = blockIdx.x, b = blockIdx.y, chalf = blockIdx.z;
    int tX = (tile % 3) * 32, tY = (tile / 3) * 32;
    int tx = threadIdx.x & 7, ty = threadIdx.x >> 3;  // 8 x 32 threads; 4 outputs each
    float* yout = chalf ? g_yb : g_ya;
    int cbase = chalf * 128;
    const float* xb = x1 + (size_t)b * 256 * HW;

    unsigned long long accA[32], accB[32];
    #pragma unroll
    for (int j = 0; j < 32; j++) { accA[j] = 0ull; accB[j] = 0ull; }

    #pragma unroll 1
    for (int c0 = 0; c0 < 128; c0 += 4) {
        __syncthreads();
        for (int i = threadIdx.x; i < 4 * 34 * 34; i += 256) {
            int cc = i / 1156, rem = i % 1156, rr = rem / 34, col = rem % 34;
            int gy = tY - 1 + rr, gx = tX - 1 + col;
            float v = 0.f;
            if ((unsigned)gy < 96u && (unsigned)gx < 96u)
                v = xb[((size_t)(cbase + c0 + cc)) * HW + gy * 96 + gx];
            in_s[cc][rr][col] = v;
        }
        for (int i = threadIdx.x; i < 4 * 32 * 9; i += 256) {
            int cc = i / 288, rem = i % 288, j = rem / 9, k = rem % 9;
            float w = __ldg(con + j * 2304 + (cbase + c0 + cc) * 9 + k);
            w_s[cc][j][k] = make_float2(w, w);
        }
        __syncthreads();

        #pragma unroll 1
        for (int cc = 0; cc < 4; cc++) {
            float va[3][6];
            #pragma unroll
            for (int rr = 0; rr < 3; rr++) {
                const float* bp = &in_s[cc][ty + rr][tx * 4];
                float4 q = *(const float4*)bp;
                float2 t = *(const float2*)(bp + 4);
                va[rr][0] = q.x; va[rr][1] = q.y; va[rr][2] = q.z;
                va[rr][3] = q.w; va[rr][4] = t.x; va[rr][5] = t.y;
            }
            unsigned long long pA[9], pB[9];
            #pragma unroll
            for (int rr = 0; rr < 3; rr++)
                #pragma unroll
                for (int kw = 0; kw < 3; kw++) {
                    pA[rr * 3 + kw] = pk2f(va[rr][kw],     va[rr][kw + 1]);
                    pB[rr * 3 + kw] = pk2f(va[rr][kw + 2], va[rr][kw + 3]);
                }
            const unsigned long long* wp = (const unsigned long long*)&w_s[cc][0][0];
            #pragma unroll
            for (int j = 0; j < 32; j++) {
                #pragma unroll
                for (int k = 0; k < 9; k++) {
                    unsigned long long w2 = wp[j * 9 + k];
                    fma2(accA[j], w2, pA[k]);
                    fma2(accB[j], w2, pB[k]);
                }
            }
        }
    }

    int gy = tY + ty, gx0 = tX + tx * 4;
    #pragma unroll
    for (int j = 0; j < 32; j++) {
        float4 r;
        upk2f(accA[j], r.x, r.y);
        upk2f(accB[j], r.z, r.w);
        *(float4*)(yout + ((size_t)(b * 32 + j) * 96 + gy) * 96 + gx0) = r;
    }
}

// ---------------- K7: out[b,o,p] = sum_j aff[b,o,j] * (ya+yb)[b,j,p] ----------------
// grid: (18 tiles of 512 pos) x 8 b; 128 thr, 4 positions per thread (2x f32x2).
__global__ void __launch_bounds__(128) mix_kernel(float* __restrict__ out) {
    __shared__ float af[8192];         // 32 KB: aff[b] scalar
    int b = blockIdx.y;
    int p0 = blockIdx.x * 512 + threadIdx.x * 4;
    for (int i = threadIdx.x; i < 8192; i += 128)
        af[i] = g_aff[(size_t)b * 8192 + i];
    __syncthreads();

    unsigned long long yA[32], yB[32];
    #pragma unroll
    for (int j = 0; j < 32; j++) {
        size_t off = ((size_t)(b * 32 + j)) * HW + p0;
        float4 a = *(const float4*)(g_ya + off);
        float4 c = *(const float4*)(g_yb + off);
        yA[j] = pk2f(a.x + c.x, a.y + c.y);
        yB[j] = pk2f(a.z + c.z, a.w + c.w);
    }
    #pragma unroll 1
    for (int o = 0; o < 256; o++) {
        unsigned long long aA = 0ull, aB = 0ull;
        const float* ao = &af[o * 32];
        #pragma unroll
        for (int j = 0; j < 32; j++) {
            unsigned long long w2 = pk2f(ao[j], ao[j]);   // uniform LDS bcast + pack
            fma2(aA, w2, yA[j]);
            fma2(aB, w2, yB[j]);
        }
        float4 r;
        upk2f(aA, r.x, r.y);
        upk2f(aB, r.z, r.w);
        *(float4*)(out + ((size_t)(b * 256 + o)) * HW + p0) = r;
    }
}

// ---------------- launch ----------------
extern "C" void kernel_launch(void* const* d_in, const int* in_sizes, int n_in,
                              void* d_out, int out_size) {
    const float* x_1 = (const float*)d_in[0];
    const float* x   = (const float*)d_in[1];
    const float* wq  = (const float*)d_in[2];
    const float* bq  = (const float*)d_in[3];
    const float* wk  = (const float*)d_in[4];
    const float* bk  = (const float*)d_in[5];
    const float* con = (const float*)d_in[6];
    float* out = (float*)d_out;

    pool_kernel <<<4096, 256>>>(x_1, x);
    projk_kernel<<<dim3(10, 8), 256>>>(wk, bk);
    s_kernel    <<<8, 32>>>();
    gmat_kernel <<<dim3(4, 8), 256>>>();
    aff_kernel  <<<dim3(16, 8), 128>>>(wq, bq);
    conv_kernel <<<dim3(9, 8, 2), 256>>>(x_1, con);
    mix_kernel  <<<dim3(18, 8), 128>>>(out);
}

// round 4
// speedup vs baseline: 1.2186x; 1.2186x over previous
#include <cuda_runtime.h>

#define B_  8
#define C_  256
#define C8  32
#define H_  96
#define W_  96
#define HW  9216
#define PP  280

typedef unsigned long long ull;

// ---------------- scratch (device globals; no allocation allowed) ----------------
__device__ float g_P1[B_*C_*PP];     // PSP(x_1)  [8,256,280]
__device__ float g_P2[B_*C_*PP];     // PSP(x)    [8,256,280]
__device__ float g_pk[B_*C8*PP];     // projk     [8,32,280]
__device__ float g_S [B_*C8];        // sum_p projk
__device__ float g_G [B_*C_*C8];     // P1 . projk^T  [8,256,32]
__device__ float g_aff[B_*C_*C8];    // sigmoid(...)  [8,256,32]
__device__ float g_ya[B_*C8*HW];     // conv partial (c 0..127)
__device__ float g_yb[B_*C8*HW];     // conv partial (c 128..255)
__device__ __align__(16) float2 g_w2[C_*C8*9];  // duplicated conv weights [c][j][k]

// ---------------- f32x2 helpers (Blackwell packed fp32) ----------------
__device__ __forceinline__ ull pk2f(float lo, float hi) {
    ull r;
    asm("mov.b64 %0, {%1, %2};" : "=l"(r) : "f"(lo), "f"(hi));
    return r;
}
__device__ __forceinline__ void upk2f(ull v, float& lo, float& hi) {
    asm("mov.b64 {%0, %1}, %2;" : "=f"(lo), "=f"(hi) : "l"(v));
}
__device__ __forceinline__ void fma2(ull& acc, ull a, ull b) {
    asm("fma.rn.f32x2 %0, %1, %2, %0;" : "+l"(acc) : "l"(a), "l"(b));
}
__device__ __forceinline__ ull add2(ull a, ull b) {
    ull r;
    asm("add.rn.f32x2 %0, %1, %2;" : "=l"(r) : "l"(a), "l"(b));
    return r;
}

// ---------------- cp.async helpers ----------------
__device__ __forceinline__ unsigned s2u(const void* p) {
    return (unsigned)__cvta_generic_to_shared(p);
}
__device__ __forceinline__ void cpa4z(unsigned d, const void* s, int sz) {
    asm volatile("cp.async.ca.shared.global [%0], [%1], 4, %2;" :: "r"(d), "l"(s), "r"(sz));
}
__device__ __forceinline__ void cpa16(unsigned d, const void* s) {
    asm volatile("cp.async.cg.shared.global [%0], [%1], 16;" :: "r"(d), "l"(s));
}
#define CP_COMMIT() asm volatile("cp.async.commit_group;" ::: "memory")
#define CP_WAIT1()  asm volatile("cp.async.wait_group 1;"  ::: "memory")
#define CP_WAIT0()  asm volatile("cp.async.wait_group 0;"  ::: "memory")

// ---------------- K0: duplicate conv weights to float2 [c][j][k] ----------------
__global__ void __launch_bounds__(256) w2prep_kernel(const float* __restrict__ con) {
    int idx = blockIdx.x * 256 + threadIdx.x;      // < 73728
    int c = idx / 288, r = idx % 288, j = r / 9, k = r % 9;
    float w = con[j * 2304 + c * 9 + k];
    g_w2[idx] = make_float2(w, w);
}

// ---------------- K1: adaptive pyramid pooling (both tensors) ----------------
__global__ void __launch_bounds__(256) pool_kernel(const float* __restrict__ x1,
                                                   const float* __restrict__ x2) {
    __shared__ float tile[96][97];
    __shared__ float rb[30][96];
    int idx = blockIdx.x;
    int sel = idx >> 11;
    int ch  = idx & 2047;
    const float* src = sel ? x2 : x1;
    float* dst = sel ? g_P2 : g_P1;

    const float4* s4 = (const float4*)(src + (size_t)ch * HW);
    for (int i = threadIdx.x; i < HW / 4; i += 256) {
        float4 v = s4[i];
        int li = i * 4, r = li / 96, c0 = li % 96;
        tile[r][c0] = v.x; tile[r][c0+1] = v.y; tile[r][c0+2] = v.z; tile[r][c0+3] = v.w;
    }
    __syncthreads();

    for (int t = threadIdx.x; t < 30 * 96; t += 256) {
        int bin = t / 96, w = t % 96, s, i;
        if      (bin == 0) { s = 1;  i = 0; }
        else if (bin < 4)  { s = 3;  i = bin - 1; }
        else if (bin < 9)  { s = 5;  i = bin - 4; }
        else if (bin < 16) { s = 7;  i = bin - 9; }
        else               { s = 14; i = bin - 16; }
        int rs = (i * 96) / s, re = ((i + 1) * 96 + s - 1) / s;
        float sum = 0.f;
        for (int h = rs; h < re; h++) sum += tile[h][w];
        rb[bin][w] = sum;
    }
    __syncthreads();

    for (int p = threadIdx.x; p < PP; p += 256) {
        int s, base, rbb;
        if      (p < 1)  { s = 1;  base = 0;  rbb = 0; }
        else if (p < 10) { s = 3;  base = 1;  rbb = 1; }
        else if (p < 35) { s = 5;  base = 10; rbb = 4; }
        else if (p < 84) { s = 7;  base = 35; rbb = 9; }
        else             { s = 14; base = 84; rbb = 16; }
        int q = p - base, i = q / s, j = q % s;
        int rs = (i * 96) / s, re = ((i + 1) * 96 + s - 1) / s;
        int cs = (j * 96) / s, ce = ((j + 1) * 96 + s - 1) / s;
        float sum = 0.f;
        for (int w = cs; w < ce; w++) sum += rb[rbb + i][w];
        dst[(size_t)ch * PP + p] = sum / (float)((re - rs) * (ce - cs));
    }
}

// ---------------- K2: projk = wk @ P2 + bk  (grid: 20 p-tiles x 8 b) ----------------
__global__ void __launch_bounds__(256) projk_kernel(const float* __restrict__ wk,
                                                    const float* __restrict__ bk) {
    __shared__ float pt[256][14];
    int b = blockIdx.y, p0 = blockIdx.x * 14;
    for (int i = threadIdx.x; i < 256 * 14; i += 256) {
        int c = i / 14, pp = i % 14;
        pt[c][pp] = g_P2[((size_t)(b * 256 + c)) * PP + p0 + pp];
    }
    __syncthreads();
    for (int oi = threadIdx.x; oi < 32 * 14; oi += 256) {
        int j = oi / 14, pp = oi % 14;
        float sum = 0.f;
        #pragma unroll 8
        for (int c = 0; c < 256; c++)
            sum += __ldg(wk + j * 256 + c) * pt[c][pp];
        g_pk[((size_t)(b * 32 + j)) * PP + p0 + pp] = bk[j] + sum;
    }
}

// ---------------- K3: S[b,j] = sum_p projk ----------------
__global__ void s_kernel() {
    int b = blockIdx.x, j = threadIdx.x;
    const float* r = g_pk + ((size_t)(b * 32 + j)) * PP;
    float s = 0.f;
    for (int p = 0; p < PP; p++) s += r[p];
    g_S[b * 32 + j] = s;
}

// ---------------- K4: G[b,c,j] = sum_p P1[b,c,p]*projk[b,j,p] ----------------
// grid: (16 c-tiles of 16) x 8 b; 128 thr: c = tile*16 + tid/8, jg = (tid&7)*4
__global__ void __launch_bounds__(128) gmat_kernel() {
    __shared__ float pk_s[32 * 281];
    int b = blockIdx.y, c = blockIdx.x * 16 + (threadIdx.x >> 3);
    int jg = (threadIdx.x & 7) * 4;
    for (int i = threadIdx.x; i < 32 * 280; i += 128)
        pk_s[(i / 280) * 281 + (i % 280)] = g_pk[(size_t)b * 32 * PP + i];
    __syncthreads();
    const float* p1 = g_P1 + ((size_t)(b * 256 + c)) * PP;
    float acc[4];
    #pragma unroll
    for (int k = 0; k < 4; k++) acc[k] = 0.f;
    #pragma unroll 4
    for (int p = 0; p < PP; p++) {
        float xv = __ldg(p1 + p);
        #pragma unroll
        for (int k = 0; k < 4; k++) acc[k] += xv * pk_s[(jg + k) * 281 + p];
    }
    #pragma unroll
    for (int k = 0; k < 4; k++)
        g_G[((size_t)(b * 256 + c)) * 32 + jg + k] = acc[k];
}

// ---------------- K5: aff = sigmoid(wq @ G + bq*S) ----------------
__global__ void __launch_bounds__(128) aff_kernel(const float* __restrict__ wq,
                                                  const float* __restrict__ bq) {
    __shared__ float Gs[256 * 33];
    int b = blockIdx.y;
    int o = blockIdx.x * 16 + (threadIdx.x >> 3);
    int cg = threadIdx.x & 7;
    for (int i = threadIdx.x; i < 8192; i += 128)
        Gs[(i >> 5) * 33 + (i & 31)] = g_G[(size_t)b * 8192 + i];
    __syncthreads();
    float acc[32];
    #pragma unroll
    for (int j = 0; j < 32; j++) acc[j] = 0.f;
    for (int cc = 0; cc < 32; cc++) {
        int c = cg + cc * 8;
        float wv = __ldg(wq + o * 256 + c);
        #pragma unroll
        for (int j = 0; j < 32; j++) acc[j] += wv * Gs[c * 33 + j];
    }
    #pragma unroll
    for (int j = 0; j < 32; j++) {
        acc[j] += __shfl_xor_sync(0xffffffffu, acc[j], 1);
        acc[j] += __shfl_xor_sync(0xffffffffu, acc[j], 2);
        acc[j] += __shfl_xor_sync(0xffffffffu, acc[j], 4);
    }
    if (cg == 0) {
        float bqo = __ldg(bq + o);
        #pragma unroll
        for (int j = 0; j < 32; j++) {
            float z = acc[j] + bqo * g_S[b * 32 + j];
            g_aff[((size_t)(b * 256 + o)) * 32 + j] = 1.f / (1.f + expf(-z));
        }
    }
}

// ---------------- K6: y = conv3x3(x_1, con), cp.async double-buffered ----------------
// grid: (9 spatial 32x32 tiles) x 8 b x 2 c-halves; 256 thr; 64 stages of 2 channels.
__global__ void __launch_bounds__(256, 1) conv_kernel(const float* __restrict__ x1) {
    __shared__ __align__(16) float  in_s[2][2][34][36];   // [buf][cc][r][col] 19584 B
    __shared__ __align__(16) float2 w_s[2][2][32][9];     // [buf][cc][j][k]    9216 B
    int tile = blockIdx.x, b = blockIdx.y, chalf = blockIdx.z;
    int tX = (tile % 3) * 32, tY = (tile / 3) * 32;
    int tx = threadIdx.x & 7, ty = threadIdx.x >> 3;      // 8 x 32; 4 outputs/thread
    int cbase = chalf * 128;
    float* yout = chalf ? g_yb : g_ya;
    const float* xb = x1 + (size_t)b * 256 * HW;

    ull accA[32], accB[32];
    #pragma unroll
    for (int j = 0; j < 32; j++) { accA[j] = 0ull; accB[j] = 0ull; }

    auto load_stage = [&](int s, int buf) {
        int c0 = cbase + s * 2;
        // input halo tile: 2 x 34 x 34 elements, zero-filled OOB
        for (int i = threadIdx.x; i < 2 * 34 * 34; i += 256) {
            int cc = i / 1156, rem = i - cc * 1156, rr = rem / 34, col = rem - rr * 34;
            int gy = tY - 1 + rr, gx = tX - 1 + col;
            int ok = ((unsigned)gy < 96u) && ((unsigned)gx < 96u);
            const float* sp = xb + (size_t)(c0 + cc) * HW + (ok ? gy * 96 + gx : 0);
            cpa4z(s2u(&in_s[buf][cc][rr][col]), sp, ok ? 4 : 0);
        }
        // duplicated weights: 2*32*9 float2 = 4608 B = 288 x 16B chunks (aligned)
        const char* wsrc = (const char*)(g_w2 + (size_t)c0 * 288);
        char* wdst = (char*)&w_s[buf][0][0][0];
        for (int i = threadIdx.x; i < 288; i += 256)
            cpa16(s2u(wdst + i * 16), wsrc + i * 16);
    };

    load_stage(0, 0);
    CP_COMMIT();

    #pragma unroll 1
    for (int s = 0; s < 64; s++) {
        if (s < 63) {
            load_stage(s + 1, (s + 1) & 1);
            CP_COMMIT();
            CP_WAIT1();
        } else {
            CP_WAIT0();
        }
        __syncthreads();

        int buf = s & 1;
        #pragma unroll
        for (int cc = 0; cc < 2; cc++) {
            float va[3][6];
            #pragma unroll
            for (int rr = 0; rr < 3; rr++) {
                const float* bp = &in_s[buf][cc][ty + rr][tx * 4];
                float4 q = *(const float4*)bp;
                float2 t = *(const float2*)(bp + 4);
                va[rr][0] = q.x; va[rr][1] = q.y; va[rr][2] = q.z;
                va[rr][3] = q.w; va[rr][4] = t.x; va[rr][5] = t.y;
            }
            ull pA[9], pB[9];
            #pragma unroll
            for (int rr = 0; rr < 3; rr++)
                #pragma unroll
                for (int kw = 0; kw < 3; kw++) {
                    pA[rr * 3 + kw] = pk2f(va[rr][kw],     va[rr][kw + 1]);
                    pB[rr * 3 + kw] = pk2f(va[rr][kw + 2], va[rr][kw + 3]);
                }
            const ull* wp = (const ull*)&w_s[buf][cc][0][0];
            #pragma unroll
            for (int j = 0; j < 32; j++) {
                #pragma unroll
                for (int k = 0; k < 9; k++) {
                    ull w2 = wp[j * 9 + k];
                    fma2(accA[j], w2, pA[k]);
                    fma2(accB[j], w2, pB[k]);
                }
            }
        }
        __syncthreads();
    }

    int gy = tY + ty, gx0 = tX + tx * 4;
    #pragma unroll
    for (int j = 0; j < 32; j++) {
        float4 r;
        upk2f(accA[j], r.x, r.y);
        upk2f(accB[j], r.z, r.w);
        *(float4*)(yout + ((size_t)(b * 32 + j) * 96 + gy) * 96 + gx0) = r;
    }
}

// ---------------- K7: out[b,o,p] = sum_j aff[b,o,j] * (ya+yb)[b,j,p] ----------------
// grid: (18 pos-tiles of 512) x 8 b x 2 o-halves; 128 thr, 4 positions/thread.
__global__ void __launch_bounds__(128) mix_kernel(float* __restrict__ out) {
    __shared__ float2 af2[128 * 32];   // 32 KB, duplicated aff for this o-half
    int b = blockIdx.y, oh = blockIdx.z;
    int p0 = blockIdx.x * 512 + threadIdx.x * 4;
    for (int i = threadIdx.x; i < 4096; i += 128) {
        float a = g_aff[(size_t)b * 8192 + oh * 4096 + i];
        af2[i] = make_float2(a, a);
    }
    __syncthreads();

    ull yA[32], yB[32];
    #pragma unroll
    for (int j = 0; j < 32; j++) {
        size_t off = ((size_t)(b * 32 + j)) * HW + p0;
        float4 a = *(const float4*)(g_ya + off);
        float4 c = *(const float4*)(g_yb + off);
        yA[j] = pk2f(a.x + c.x, a.y + c.y);
        yB[j] = pk2f(a.z + c.z, a.w + c.w);
    }
    #pragma unroll 1
    for (int o = 0; o < 128; o++) {
        const ull* ao = (const ull*)&af2[o * 32];
        ull s0 = 0ull, s1 = 0ull, t0 = 0ull, t1 = 0ull;
        #pragma unroll
        for (int j = 0; j < 32; j += 2) {
            ull w0 = ao[j], w1 = ao[j + 1];
            fma2(s0, w0, yA[j]);     fma2(t0, w0, yB[j]);
            fma2(s1, w1, yA[j + 1]); fma2(t1, w1, yB[j + 1]);
        }
        ull sa = add2(s0, s1), sb = add2(t0, t1);
        float4 r;
        upk2f(sa, r.x, r.y);
        upk2f(sb, r.z, r.w);
        *(float4*)(out + ((size_t)(b * 256 + oh * 128 + o)) * HW + p0) = r;
    }
}

// ---------------- launch ----------------
extern "C" void kernel_launch(void* const* d_in, const int* in_sizes, int n_in,
                              void* d_out, int out_size) {
    const float* x_1 = (const float*)d_in[0];
    const float* x   = (const float*)d_in[1];
    const float* wq  = (const float*)d_in[2];
    const float* bq  = (const float*)d_in[3];
    const float* wk  = (const float*)d_in[4];
    const float* bk  = (const float*)d_in[5];
    const float* con = (const float*)d_in[6];
    float* out = (float*)d_out;

    w2prep_kernel<<<288, 256>>>(con);
    pool_kernel  <<<4096, 256>>>(x_1, x);
    projk_kernel <<<dim3(20, 8), 256>>>(wk, bk);
    s_kernel     <<<8, 32>>>();
    gmat_kernel  <<<dim3(16, 8), 128>>>();
    aff_kernel   <<<dim3(16, 8), 128>>>(wq, bq);
    conv_kernel  <<<dim3(9, 8, 2), 256>>>(x_1);
    mix_kernel   <<<dim3(18, 8, 2), 128>>>(out);
}

// round 5
// speedup vs baseline: 1.2830x; 1.0528x over previous
#include <cuda_runtime.h>

#define B_  8
#define C_  256
#define C8  32
#define H_  96
#define W_  96
#define HW  9216
#define PP  280

typedef unsigned long long ull;

// ---------------- scratch (device globals; no allocation allowed) ----------------
__device__ float g_P1[B_*C_*PP];       // PSP(x_1)  [8,256,280]
__device__ float g_P2[B_*C_*PP];       // PSP(x)    [8,256,280]
__device__ float g_pk[B_*C8*PP];       // projk     [8,32,280]
__device__ float g_Sp[B_*20*C8];       // per-tile partial sums of projk
__device__ float g_G [B_*C_*C8];       // P1 . projk^T  [8,256,32]
__device__ float g_aff[B_*C_*C8];      // sigmoid(...)  [8,256,32]
__device__ float g_ya[B_*C8*HW];       // conv partial (c 0..127)
__device__ float g_yb[B_*C8*HW];       // conv partial (c 128..255)
__device__ __align__(16) float2 g_w2[C_*C8*9];  // duplicated conv weights [c][j][k]

// ---------------- f32x2 helpers ----------------
__device__ __forceinline__ ull pk2f(float lo, float hi) {
    ull r;
    asm("mov.b64 %0, {%1, %2};" : "=l"(r) : "f"(lo), "f"(hi));
    return r;
}
__device__ __forceinline__ void upk2f(ull v, float& lo, float& hi) {
    asm("mov.b64 {%0, %1}, %2;" : "=f"(lo), "=f"(hi) : "l"(v));
}
__device__ __forceinline__ void fma2(ull& acc, ull a, ull b) {
    asm("fma.rn.f32x2 %0, %1, %2, %0;" : "+l"(acc) : "l"(a), "l"(b));
}
__device__ __forceinline__ ull add2(ull a, ull b) {
    ull r;
    asm("add.rn.f32x2 %0, %1, %2;" : "=l"(r) : "l"(a), "l"(b));
    return r;
}

// ---------------- cp.async helpers ----------------
__device__ __forceinline__ unsigned s2u(const void* p) {
    return (unsigned)__cvta_generic_to_shared(p);
}
__device__ __forceinline__ void cpa4z(unsigned d, const void* s, int sz) {
    asm volatile("cp.async.ca.shared.global [%0], [%1], 4, %2;" :: "r"(d), "l"(s), "r"(sz));
}
__device__ __forceinline__ void cpa16(unsigned d, const void* s) {
    asm volatile("cp.async.cg.shared.global [%0], [%1], 16;" :: "r"(d), "l"(s));
}
#define CP_COMMIT() asm volatile("cp.async.commit_group;" ::: "memory")
#define CP_WAIT1()  asm volatile("cp.async.wait_group 1;"  ::: "memory")
#define CP_WAIT0()  asm volatile("cp.async.wait_group 0;"  ::: "memory")

// ---------------- K0: duplicate conv weights to float2 [c][j][k] ----------------
__global__ void __launch_bounds__(256) w2prep_kernel(const float* __restrict__ con) {
    int idx = blockIdx.x * 256 + threadIdx.x;      // < 73728
    int c = idx / 288, r = idx % 288, j = r / 9, k = r % 9;
    float w = con[j * 2304 + c * 9 + k];
    g_w2[idx] = make_float2(w, w);
}

// ---------------- K1: adaptive pyramid pooling (both tensors) ----------------
__global__ void __launch_bounds__(256) pool_kernel(const float* __restrict__ x1,
                                                   const float* __restrict__ x2) {
    __shared__ float tile[96][97];
    __shared__ float rb[30][96];
    int idx = blockIdx.x;
    int sel = idx >> 11;
    int ch  = idx & 2047;
    const float* src = sel ? x2 : x1;
    float* dst = sel ? g_P2 : g_P1;

    const float4* s4 = (const float4*)(src + (size_t)ch * HW);
    for (int i = threadIdx.x; i < HW / 4; i += 256) {
        float4 v = s4[i];
        int li = i * 4, r = li / 96, c0 = li % 96;
        tile[r][c0] = v.x; tile[r][c0+1] = v.y; tile[r][c0+2] = v.z; tile[r][c0+3] = v.w;
    }
    __syncthreads();

    for (int t = threadIdx.x; t < 30 * 96; t += 256) {
        int bin = t / 96, w = t % 96, s, i;
        if      (bin == 0) { s = 1;  i = 0; }
        else if (bin < 4)  { s = 3;  i = bin - 1; }
        else if (bin < 9)  { s = 5;  i = bin - 4; }
        else if (bin < 16) { s = 7;  i = bin - 9; }
        else               { s = 14; i = bin - 16; }
        int rs = (i * 96) / s, re = ((i + 1) * 96 + s - 1) / s;
        float sum = 0.f;
        for (int h = rs; h < re; h++) sum += tile[h][w];
        rb[bin][w] = sum;
    }
    __syncthreads();

    for (int p = threadIdx.x; p < PP; p += 256) {
        int s, base, rbb;
        if      (p < 1)  { s = 1;  base = 0;  rbb = 0; }
        else if (p < 10) { s = 3;  base = 1;  rbb = 1; }
        else if (p < 35) { s = 5;  base = 10; rbb = 4; }
        else if (p < 84) { s = 7;  base = 35; rbb = 9; }
        else             { s = 14; base = 84; rbb = 16; }
        int q = p - base, i = q / s, j = q % s;
        int rs = (i * 96) / s, re = ((i + 1) * 96 + s - 1) / s;
        int cs = (j * 96) / s, ce = ((j + 1) * 96 + s - 1) / s;
        float sum = 0.f;
        for (int w = cs; w < ce; w++) sum += rb[rbb + i][w];
        dst[(size_t)ch * PP + p] = sum / (float)((re - rs) * (ce - cs));
    }
}

// ---------------- K2: projk = wk @ P2 + bk, plus per-tile S partials ----------------
__global__ void __launch_bounds__(256) projk_kernel(const float* __restrict__ wk,
                                                    const float* __restrict__ bk) {
    __shared__ float pt[256][14];
    __shared__ float red[32][14];
    int b = blockIdx.y, p0 = blockIdx.x * 14;
    for (int i = threadIdx.x; i < 256 * 14; i += 256) {
        int c = i / 14, pp = i % 14;
        pt[c][pp] = g_P2[((size_t)(b * 256 + c)) * PP + p0 + pp];
    }
    __syncthreads();
    for (int oi = threadIdx.x; oi < 32 * 14; oi += 256) {
        int j = oi / 14, pp = oi % 14;
        float sum = 0.f;
        #pragma unroll 8
        for (int c = 0; c < 256; c++)
            sum += __ldg(wk + j * 256 + c) * pt[c][pp];
        float v = bk[j] + sum;
        g_pk[((size_t)(b * 32 + j)) * PP + p0 + pp] = v;
        red[j][pp] = v;
    }
    __syncthreads();
    if (threadIdx.x < 32) {
        float s = 0.f;
        #pragma unroll
        for (int pp = 0; pp < 14; pp++) s += red[threadIdx.x][pp];
        g_Sp[((size_t)b * 20 + blockIdx.x) * 32 + threadIdx.x] = s;
    }
}

// ---------------- K4: G[b,c,j] = sum_p P1[b,c,p]*projk[b,j,p] ----------------
__global__ void __launch_bounds__(128) gmat_kernel() {
    __shared__ float pk_s[32 * 281];
    int b = blockIdx.y, c = blockIdx.x * 16 + (threadIdx.x >> 3);
    int jg = (threadIdx.x & 7) * 4;
    for (int i = threadIdx.x; i < 32 * 280; i += 128)
        pk_s[(i / 280) * 281 + (i % 280)] = g_pk[(size_t)b * 32 * PP + i];
    __syncthreads();
    const float* p1 = g_P1 + ((size_t)(b * 256 + c)) * PP;
    float acc[4];
    #pragma unroll
    for (int k = 0; k < 4; k++) acc[k] = 0.f;
    #pragma unroll 4
    for (int p = 0; p < PP; p++) {
        float xv = __ldg(p1 + p);
        #pragma unroll
        for (int k = 0; k < 4; k++) acc[k] += xv * pk_s[(jg + k) * 281 + p];
    }
    #pragma unroll
    for (int k = 0; k < 4; k++)
        g_G[((size_t)(b * 256 + c)) * 32 + jg + k] = acc[k];
}

// ---------------- K5: aff = sigmoid(wq @ G + bq*S) ----------------
__global__ void __launch_bounds__(128) aff_kernel(const float* __restrict__ wq,
                                                  const float* __restrict__ bq) {
    __shared__ float Gs[256 * 33];
    __shared__ float Ss[32];
    int b = blockIdx.y;
    int o = blockIdx.x * 16 + (threadIdx.x >> 3);
    int cg = threadIdx.x & 7;
    if (threadIdx.x < 32) {
        float s = 0.f;
        #pragma unroll
        for (int t = 0; t < 20; t++)
            s += g_Sp[((size_t)b * 20 + t) * 32 + threadIdx.x];
        Ss[threadIdx.x] = s;
    }
    for (int i = threadIdx.x; i < 8192; i += 128)
        Gs[(i >> 5) * 33 + (i & 31)] = g_G[(size_t)b * 8192 + i];
    __syncthreads();
    float acc[32];
    #pragma unroll
    for (int j = 0; j < 32; j++) acc[j] = 0.f;
    for (int cc = 0; cc < 32; cc++) {
        int c = cg + cc * 8;
        float wv = __ldg(wq + o * 256 + c);
        #pragma unroll
        for (int j = 0; j < 32; j++) acc[j] += wv * Gs[c * 33 + j];
    }
    #pragma unroll
    for (int j = 0; j < 32; j++) {
        acc[j] += __shfl_xor_sync(0xffffffffu, acc[j], 1);
        acc[j] += __shfl_xor_sync(0xffffffffu, acc[j], 2);
        acc[j] += __shfl_xor_sync(0xffffffffu, acc[j], 4);
    }
    if (cg == 0) {
        float bqo = __ldg(bq + o);
        #pragma unroll
        for (int j = 0; j < 32; j++) {
            float z = acc[j] + bqo * Ss[j];
            g_aff[((size_t)(b * 256 + o)) * 32 + j] = 1.f / (1.f + expf(-z));
        }
    }
}

// ---------------- K6: conv3x3, triple-buffered cp.async, 16j x 8px per thread ----------------
// grid: (9 spatial 32x32 tiles) x 8 b x 2 c-halves; 256 thr; 64 stages of 2 channels.
// thread: jh = tid>>7 (16 j), ty = (tid&127)>>2 (row), tx = tid&3 (8-px group).
__global__ void __launch_bounds__(256, 1) conv_kernel(const float* __restrict__ x1) {
    __shared__ __align__(16) float  in_s[3][2][34][36];   // 29376 B
    __shared__ __align__(16) float2 w_s[3][2][32][9];     // 13824 B  (total 43200 B)
    int tile = blockIdx.x, b = blockIdx.y, chalf = blockIdx.z;
    int tX = (tile % 3) * 32, tY = (tile / 3) * 32;
    int jh = threadIdx.x >> 7;
    int rem = threadIdx.x & 127;
    int ty = rem >> 2, tx = rem & 3;
    int cbase = chalf * 128;
    float* yout = chalf ? g_yb : g_ya;
    const float* xb = x1 + (size_t)b * 256 * HW;

    ull acc[16][4];
    #pragma unroll
    for (int j = 0; j < 16; j++)
        #pragma unroll
        for (int u = 0; u < 4; u++) acc[j][u] = 0ull;

    auto load_stage = [&](int s, int buf) {
        int c0 = cbase + s * 2;
        for (int i = threadIdx.x; i < 2 * 34 * 34; i += 256) {
            int cc = i / 1156, r2 = i - cc * 1156, rr = r2 / 34, col = r2 - rr * 34;
            int gy = tY - 1 + rr, gx = tX - 1 + col;
            int ok = ((unsigned)gy < 96u) && ((unsigned)gx < 96u);
            const float* sp = xb + (size_t)(c0 + cc) * HW + (ok ? gy * 96 + gx : 0);
            cpa4z(s2u(&in_s[buf][cc][rr][col]), sp, ok ? 4 : 0);
        }
        const char* wsrc = (const char*)(g_w2 + (size_t)c0 * 288);
        char* wdst = (char*)&w_s[buf][0][0][0];
        for (int i = threadIdx.x; i < 288; i += 256)
            cpa16(s2u(wdst + i * 16), wsrc + i * 16);
    };

    load_stage(0, 0); CP_COMMIT();
    load_stage(1, 1); CP_COMMIT();

    #pragma unroll 1
    for (int s = 0; s < 64; s++) {
        if (s < 63) { CP_WAIT1(); } else { CP_WAIT0(); }
        __syncthreads();
        if (s < 62) {
            int sn = s + 2;
            load_stage(sn, sn - (sn / 3) * 3);
            CP_COMMIT();
        }
        int buf = s - (s / 3) * 3;

        #pragma unroll
        for (int cc = 0; cc < 2; cc++) {
            float v[3][10];
            #pragma unroll
            for (int rr = 0; rr < 3; rr++) {
                const float* bp = &in_s[buf][cc][ty + rr][tx * 8];
                float4 a = *(const float4*)bp;
                float4 d = *(const float4*)(bp + 4);
                float2 e = *(const float2*)(bp + 8);
                v[rr][0] = a.x; v[rr][1] = a.y; v[rr][2] = a.z; v[rr][3] = a.w;
                v[rr][4] = d.x; v[rr][5] = d.y; v[rr][6] = d.z; v[rr][7] = d.w;
                v[rr][8] = e.x; v[rr][9] = e.y;
            }
            ull p[9][4];
            #pragma unroll
            for (int rr = 0; rr < 3; rr++)
                #pragma unroll
                for (int kw = 0; kw < 3; kw++)
                    #pragma unroll
                    for (int u = 0; u < 4; u++)
                        p[rr * 3 + kw][u] = pk2f(v[rr][kw + 2 * u], v[rr][kw + 2 * u + 1]);
            const ull* wp = (const ull*)&w_s[buf][cc][jh * 16][0];
            #pragma unroll
            for (int j = 0; j < 16; j++) {
                #pragma unroll
                for (int k = 0; k < 9; k++) {
                    ull w2 = wp[j * 9 + k];
                    #pragma unroll
                    for (int u = 0; u < 4; u++) fma2(acc[j][u], w2, p[k][u]);
                }
            }
        }
    }

    int gy = tY + ty, gx0 = tX + tx * 8;
    #pragma unroll
    for (int j = 0; j < 16; j++) {
        float4 r0, r1;
        upk2f(acc[j][0], r0.x, r0.y);
        upk2f(acc[j][1], r0.z, r0.w);
        upk2f(acc[j][2], r1.x, r1.y);
        upk2f(acc[j][3], r1.z, r1.w);
        float* op = yout + ((size_t)(b * 32 + jh * 16 + j) * 96 + gy) * 96 + gx0;
        *(float4*)op = r0;
        *(float4*)(op + 4) = r1;
    }
}

// ---------------- K7: out[b,o,p] = sum_j aff[b,o,j] * (ya+yb)[b,j,p] ----------------
__global__ void __launch_bounds__(128) mix_kernel(float* __restrict__ out) {
    __shared__ float2 af2[128 * 32];   // 32 KB
    int b = blockIdx.y, oh = blockIdx.z;
    int p0 = blockIdx.x * 512 + threadIdx.x * 4;
    for (int i = threadIdx.x; i < 4096; i += 128) {
        float a = g_aff[(size_t)b * 8192 + oh * 4096 + i];
        af2[i] = make_float2(a, a);
    }
    __syncthreads();

    ull yA[32], yB[32];
    #pragma unroll
    for (int j = 0; j < 32; j++) {
        size_t off = ((size_t)(b * 32 + j)) * HW + p0;
        float4 a = *(const float4*)(g_ya + off);
        float4 c = *(const float4*)(g_yb + off);
        yA[j] = pk2f(a.x + c.x, a.y + c.y);
        yB[j] = pk2f(a.z + c.z, a.w + c.w);
    }
    #pragma unroll 1
    for (int o = 0; o < 128; o++) {
        const ull* ao = (const ull*)&af2[o * 32];
        ull s0 = 0ull, s1 = 0ull, t0 = 0ull, t1 = 0ull;
        #pragma unroll
        for (int j = 0; j < 32; j += 2) {
            ull w0 = ao[j], w1 = ao[j + 1];
            fma2(s0, w0, yA[j]);     fma2(t0, w0, yB[j]);
            fma2(s1, w1, yA[j + 1]); fma2(t1, w1, yB[j + 1]);
        }
        ull sa = add2(s0, s1), sb = add2(t0, t1);
        float4 r;
        upk2f(sa, r.x, r.y);
        upk2f(sb, r.z, r.w);
        *(float4*)(out + ((size_t)(b * 256 + oh * 128 + o)) * HW + p0) = r;
    }
}

// ---------------- launch (conv placed at launch index 3 for ncu visibility) ----------------
extern "C" void kernel_launch(void* const* d_in, const int* in_sizes, int n_in,
                              void* d_out, int out_size) {
    const float* x_1 = (const float*)d_in[0];
    const float* x   = (const float*)d_in[1];
    const float* wq  = (const float*)d_in[2];
    const float* bq  = (const float*)d_in[3];
    const float* wk  = (const float*)d_in[4];
    const float* bk  = (const float*)d_in[5];
    const float* con = (const float*)d_in[6];
    float* out = (float*)d_out;

    w2prep_kernel<<<288, 256>>>(con);
    pool_kernel  <<<4096, 256>>>(x_1, x);
    projk_kernel <<<dim3(20, 8), 256>>>(wk, bk);
    conv_kernel  <<<dim3(9, 8, 2), 256>>>(x_1);      // launch idx 3 -> profiled
    gmat_kernel  <<<dim3(16, 8), 128>>>();
    aff_kernel   <<<dim3(16, 8), 128>>>(wq, bq);
    mix_kernel   <<<dim3(18, 8, 2), 128>>>(out);
}